// round 16
// baseline (speedup 1.0000x reference)
#include <cuda_runtime.h>
#include <math.h>
#include <stdint.h>

// ---------------------------------------------------------------------------
// LFQ forward, B=4, DIM=512, T=2048, codebook_dim=14, NB_CODE=16384
// d_out layout (float32): out[4*512*2048] | indices[4*2048] | aux_loss[1]
// K1: in-proj (R12 reg-batched, measured 14.4us) + mid + half-products
// K2: avg-GEMM (40 blocks, pipelined f32x2) || outproj (256 blocks) = 296 grid
// K3: cred (4-way p-split, 256 blocks) + final
// ---------------------------------------------------------------------------

#define DIM_ 512
#define T_   2048
#define N_   8192
#define C_   14
#define J_   16384
#define OUT_IDX  4194304
#define OUT_LOSS 4202496
#define ABLK 40            // avg-GEMM blocks (fewer partials)
#define OBLK 256           // outproj blocks (32 d-rows each)
#define K1B  256           // K1 blocks
#define SPB  32            // samples per K1 block
#define CBLK 256           // K3 blocks

// Static scratch (no allocations allowed)
__device__ int      g_idx[N_];
__device__ float    g_Lo[N_ * 128];        // low  7-bit half products (jl, c=13..7)
__device__ float    g_Hi[N_ * 128];        // high 7-bit half products (jh, c=6..0)
__device__ float    g_Ap[2 * K1B];         // K1 blocks x {commit, entropy}
__device__ float    g_Bp[ABLK * J_];       // partial avg_prob sums (2.6MB)
__device__ float    g_Cp[CBLK];            // codebook-entropy partials
__device__ unsigned g_cnt;                 // K3 last-block counter (reset by K1)

__device__ __forceinline__ unsigned long long fma_f32x2(unsigned long long a,
                                                        unsigned long long b,
                                                        unsigned long long c) {
    unsigned long long d;
    asm("fma.rn.f32x2 %0, %1, %2, %3;" : "=l"(d) : "l"(a), "l"(b), "l"(c));
    return d;
}

// ---------------------------------------------------------------------------
// K1: grid = 256 blocks x 256 threads, 32 samples/block.  (R12 measured-best)
// Thread (chunk = t>>3 in [0,32), grp = t&7) accumulates 4 samples x 14 c
// over 16 d.  Loads batched 8-deep for MLP (explicit xv[8] buffer).
// ---------------------------------------------------------------------------
__global__ void __launch_bounds__(256, 2) k_in_mid(const float* __restrict__ x,
                                                   const float* __restrict__ Win,
                                                   const float* __restrict__ bin,
                                                   float* __restrict__ dout) {
    __shared__ __align__(16) float sbuf[8192];   // phase A: ws[512][16]; B: P[16][14][32]
    __shared__ float pbuf[SPB][16];
    __shared__ float cbuf[SPB][14];
    __shared__ float ebuf[SPB][14];
    __shared__ int   ibuf[SPB][14];

    int t = threadIdx.x;
    if (blockIdx.x == 0 && t == 0) g_cnt = 0;   // reset K3's counter each call

    // ws[d][c] = Win[c][d]  (transpose; reads coalesced over d)
    float (*ws)[16] = (float(*)[16])sbuf;
    for (int i = t; i < C_ * DIM_; i += 256) {
        int c = i >> 9, d = i & 511;
        ws[d][c] = Win[i];
    }
    __syncthreads();

    int chunk = t >> 3;                 // 32 chunks x 16 d
    int grp   = t & 7;                  // 8 groups x 4 samples
    int n0    = blockIdx.x * SPB;
    int nb    = n0 + grp * 4;           // first of this thread's 4 samples
    int b     = nb >> 11, tt = nb & 2047;
    const float* xp = x + ((size_t)(b * DIM_ + chunk * 16)) * T_ + tt;

    float4 acc[C_];
#pragma unroll
    for (int c = 0; c < C_; c++) acc[c] = make_float4(0.f, 0.f, 0.f, 0.f);

    float4 xv[8];
#pragma unroll
    for (int half = 0; half < 2; half++) {
        // batched loads: 8 independent LDG.128 in flight
#pragma unroll
        for (int i = 0; i < 8; i++)
            xv[i] = *reinterpret_cast<const float4*>(xp + (size_t)(half * 8 + i) * T_);
        // consume
#pragma unroll
        for (int i = 0; i < 8; i++) {
            const float4* w4 = reinterpret_cast<const float4*>(ws[chunk * 16 + half * 8 + i]);
            float4 w0 = w4[0], w1 = w4[1], w2 = w4[2], w3 = w4[3];
            float w[C_] = {w0.x, w0.y, w0.z, w0.w, w1.x, w1.y, w1.z, w1.w,
                           w2.x, w2.y, w2.z, w2.w, w3.x, w3.y};
#pragma unroll
            for (int c = 0; c < C_; c++) {
                acc[c].x += w[c] * xv[i].x;
                acc[c].y += w[c] * xv[i].y;
                acc[c].z += w[c] * xv[i].z;
                acc[c].w += w[c] * xv[i].w;
            }
        }
    }

    // ---- chunk fold 32 -> 16 in smem (reuse sbuf; all ws reads done) ----
    // P[ch][c][s] at sbuf[ch*448 + c*32 + s], ch in [0,16)
    __syncthreads();
    if (chunk >= 16) {
        float* base = sbuf + (chunk - 16) * 448 + grp * 4;
#pragma unroll
        for (int c = 0; c < C_; c++)
            *reinterpret_cast<float4*>(base + c * 32) = acc[c];
    }
    __syncthreads();
    if (chunk < 16) {
        float* base = sbuf + chunk * 448 + grp * 4;
#pragma unroll
        for (int c = 0; c < C_; c++) {
            float4 p = *reinterpret_cast<const float4*>(base + c * 32);
            acc[c].x += p.x; acc[c].y += p.y; acc[c].z += p.z; acc[c].w += p.w;
            *reinterpret_cast<float4*>(base + c * 32) = acc[c];
        }
    }
    __syncthreads();

    // ---- mid: 448 (s,c) pairs over 256 threads (2 rounds) ----
#pragma unroll
    for (int r = 0; r < 2; r++) {
        int p = t + r * 256;
        if (p < SPB * C_) {
            int c = p >> 5, s = p & 31;
            float hv = bin[c];
#pragma unroll
            for (int ch = 0; ch < 16; ch++) hv += sbuf[ch * 448 + c * 32 + s];
            bool  pos = hv > 0.f;
            float q   = pos ? 1.f : -1.f;
            float d   = hv - q;
            float z   = __expf(-400.f * fabsf(hv));   // sigmoid(400h) small-side-safe
            float pb  = 1.f / (1.f + z);
            float psm = z * pb;
            float e   = -pb * __logf(pb);
            if (psm > 0.f) e -= psm * __logf(psm);
            pbuf[s][c] = pos ? pb : psm;
            cbuf[s][c] = d * d;
            ebuf[s][c] = e;
            ibuf[s][c] = pos ? (1 << (13 - c)) : 0;
        }
    }
    __syncthreads();

    // ---- per-sample combine (warp 0) + block loss reduction ----
    if (t < SPB) {
        int idx = 0;
        float cm = 0.f, en = 0.f;
#pragma unroll
        for (int c = 0; c < C_; c++) {
            idx |= ibuf[t][c];
            cm  += cbuf[t][c];
            en  += ebuf[t][c];
        }
        g_idx[n0 + t] = idx;
        dout[OUT_IDX + n0 + t] = (float)idx;
#pragma unroll
        for (int o = 16; o > 0; o >>= 1) {
            cm += __shfl_down_sync(0xffffffffu, cm, o);
            en += __shfl_down_sync(0xffffffffu, en, o);
        }
        if (t == 0) { g_Ap[blockIdx.x * 2] = cm; g_Ap[blockIdx.x * 2 + 1] = en; }
    }

    // ---- production: warp w -> samples w*4..w*4+3 ----
    // Lo: j bit k (k<7) <-> c = 13-k.  Hi: jh bit k <-> c = 6-k.
    {
        int warp = t >> 5, lane = t & 31;
#pragma unroll
        for (int si = 0; si < 4; si++) {
            int ss = warp * 4 + si;
            float lowL = 1.f, lowH = 1.f;
#pragma unroll
            for (int k = 0; k < 5; k++) {
                float pL = pbuf[ss][13 - k];
                float pH = pbuf[ss][6 - k];
                bool bit = (lane >> k) & 1;
                lowL *= bit ? pL : (1.f - pL);
                lowH *= bit ? pH : (1.f - pH);
            }
            float p5L = pbuf[ss][8], p6L = pbuf[ss][7];
            float p5H = pbuf[ss][1], p6H = pbuf[ss][0];
            float qL[4] = { (1.f - p5L) * (1.f - p6L), p5L * (1.f - p6L),
                            (1.f - p5L) * p6L,         p5L * p6L };
            float qH[4] = { (1.f - p5H) * (1.f - p6H), p5H * (1.f - p6H),
                            (1.f - p5H) * p6H,         p5H * p6H };
            float* lp = g_Lo + (size_t)(n0 + ss) * 128 + lane;
            float* hp = g_Hi + (size_t)(n0 + ss) * 128 + lane;
#pragma unroll
            for (int q = 0; q < 4; q++) {
                lp[q * 32] = lowL * qL[q];
                hp[q * 32] = lowH * qH[q];
            }
        }
    }
}

// ---------------------------------------------------------------------------
// K2: blocks 0..39 = avg-GEMM (f32x2, 2-sample pipelined),
//     blocks 40..295 = outproj (32 d-rows).  grid = 296 = one exact wave.
// ---------------------------------------------------------------------------
__global__ void __launch_bounds__(512, 2) k_out_avg(const float* __restrict__ Wout,
                                                    const float* __restrict__ bout,
                                                    float* __restrict__ out) {
    __shared__ float ws2[32][16];
    __shared__ float bo[32];
    int t = threadIdx.x;

    if (blockIdx.x < ABLK) {
        // ---- avg outer product, f32x2-packed, 2 samples per iter ----
        int bb = blockIdx.x;
        int ns = (bb * N_) / ABLK;
        int ne = ((bb + 1) * N_) / ABLK;
        int cnt = ne - ns;
        int jl0 = (t & 31) * 4;
        int jh0 = (t >> 5) * 8;

        const float* lo = g_Lo + (size_t)ns * 128 + jl0;
        const float* hi = g_Hi + (size_t)ns * 128 + jh0;

        unsigned long long A[4][4];
#pragma unroll
        for (int p = 0; p < 4; p++)
#pragma unroll
            for (int j = 0; j < 4; j++) A[p][j] = 0ull;

        int k = 0;
        for (; k + 1 < cnt; k += 2, lo += 256, hi += 256) {
            // issue all 6 loads first (MLP)
            float4     la   = *reinterpret_cast<const float4*>(lo);
            ulonglong2 ha01 = *reinterpret_cast<const ulonglong2*>(hi);
            ulonglong2 ha23 = *reinterpret_cast<const ulonglong2*>(hi + 4);
            float4     lb   = *reinterpret_cast<const float4*>(lo + 128);
            ulonglong2 hb01 = *reinterpret_cast<const ulonglong2*>(hi + 128);
            ulonglong2 hb23 = *reinterpret_cast<const ulonglong2*>(hi + 132);

            unsigned long long hpa[4] = {ha01.x, ha01.y, ha23.x, ha23.y};
            unsigned long long lda[4];
            asm("mov.b64 %0, {%1, %1};" : "=l"(lda[0]) : "f"(la.x));
            asm("mov.b64 %0, {%1, %1};" : "=l"(lda[1]) : "f"(la.y));
            asm("mov.b64 %0, {%1, %1};" : "=l"(lda[2]) : "f"(la.z));
            asm("mov.b64 %0, {%1, %1};" : "=l"(lda[3]) : "f"(la.w));
#pragma unroll
            for (int p = 0; p < 4; p++)
#pragma unroll
                for (int j = 0; j < 4; j++)
                    A[p][j] = fma_f32x2(hpa[p], lda[j], A[p][j]);

            unsigned long long hpb[4] = {hb01.x, hb01.y, hb23.x, hb23.y};
            unsigned long long ldb[4];
            asm("mov.b64 %0, {%1, %1};" : "=l"(ldb[0]) : "f"(lb.x));
            asm("mov.b64 %0, {%1, %1};" : "=l"(ldb[1]) : "f"(lb.y));
            asm("mov.b64 %0, {%1, %1};" : "=l"(ldb[2]) : "f"(lb.z));
            asm("mov.b64 %0, {%1, %1};" : "=l"(ldb[3]) : "f"(lb.w));
#pragma unroll
            for (int p = 0; p < 4; p++)
#pragma unroll
                for (int j = 0; j < 4; j++)
                    A[p][j] = fma_f32x2(hpb[p], ldb[j], A[p][j]);
        }
        if (k < cnt) {   // odd tail
            float4     la   = *reinterpret_cast<const float4*>(lo);
            ulonglong2 ha01 = *reinterpret_cast<const ulonglong2*>(hi);
            ulonglong2 ha23 = *reinterpret_cast<const ulonglong2*>(hi + 4);
            unsigned long long hpa[4] = {ha01.x, ha01.y, ha23.x, ha23.y};
            unsigned long long lda[4];
            asm("mov.b64 %0, {%1, %1};" : "=l"(lda[0]) : "f"(la.x));
            asm("mov.b64 %0, {%1, %1};" : "=l"(lda[1]) : "f"(la.y));
            asm("mov.b64 %0, {%1, %1};" : "=l"(lda[2]) : "f"(la.z));
            asm("mov.b64 %0, {%1, %1};" : "=l"(lda[3]) : "f"(la.w));
#pragma unroll
            for (int p = 0; p < 4; p++)
#pragma unroll
                for (int j = 0; j < 4; j++)
                    A[p][j] = fma_f32x2(hpa[p], lda[j], A[p][j]);
        }

        float* bp = g_Bp + (size_t)bb * J_;
#pragma unroll
        for (int p = 0; p < 4; p++) {
            float r0[4], r1[4];
#pragma unroll
            for (int j = 0; j < 4; j++)
                asm("mov.b64 {%0, %1}, %2;" : "=f"(r0[j]), "=f"(r1[j]) : "l"(A[p][j]));
            *reinterpret_cast<float4*>(&bp[(jh0 + 2 * p) * 128 + jl0]) =
                make_float4(r0[0], r0[1], r0[2], r0[3]);
            *reinterpret_cast<float4*>(&bp[(jh0 + 2 * p + 1) * 128 + jl0]) =
                make_float4(r1[0], r1[1], r1[2], r1[3]);
        }
    } else {
        // ---- out-projection: 256 blocks, thread = sample, 32 d-rows ----
        int ob    = blockIdx.x - ABLK;
        int hch   = ob & 15;                 // 16 chunks of 32 d
        int tile  = ob >> 4;                 // 16 tiles of 512 samples
        int d0    = hch * 32;
        for (int i = t; i < 32 * 16; i += 512) {
            int dd = i >> 4, c = i & 15;
            ws2[dd][c] = (c < C_) ? Wout[(d0 + dd) * C_ + c] : 0.f;
        }
        if (t < 32) bo[t] = bout[d0 + t];
        __syncthreads();

        int n = tile * 512 + t;
        int b = n >> 11, tt = n & 2047;
        int idx = g_idx[n];
        float sv[C_];
#pragma unroll
        for (int c = 0; c < C_; c++) sv[c] = ((idx >> (13 - c)) & 1) ? 1.f : -1.f;

        float* op = out + ((size_t)(b * DIM_ + d0)) * T_ + tt;
#pragma unroll 2
        for (int dd = 0; dd < 32; dd++) {
            const float4* w4 = reinterpret_cast<const float4*>(ws2[dd]);
            float4 w0 = w4[0], w1 = w4[1], w2 = w4[2], w3 = w4[3];
            float r = bo[dd];
            r += w0.x * sv[0]  + w0.y * sv[1]  + w0.z * sv[2]  + w0.w * sv[3];
            r += w1.x * sv[4]  + w1.y * sv[5]  + w1.z * sv[6]  + w1.w * sv[7];
            r += w2.x * sv[8]  + w2.y * sv[9]  + w2.z * sv[10] + w2.w * sv[11];
            r += w3.x * sv[12] + w3.y * sv[13];
            op[(size_t)dd * T_] = r;
        }
    }
}

// ---------------------------------------------------------------------------
// K3: reduce g_Bp (40 partials) -> avg_prob -> entropy; last block combines.
// grid = 256 blocks x 256 threads; 64 e-slots/block x 4 p-groups of 10.
// ---------------------------------------------------------------------------
__global__ void __launch_bounds__(256) k_cred_final(float* __restrict__ dout) {
    int t = threadIdx.x;
    int e = blockIdx.x * 64 + (t & 63);
    int g = t >> 6;                          // 4 groups x 10 partials
    float sum = 0.f;
#pragma unroll
    for (int p = g * 10; p < g * 10 + 10; p++)
        sum += g_Bp[(size_t)p * J_ + e];

    __shared__ float sm[256];
    __shared__ float sr[64];
    __shared__ unsigned islast;
    sm[t] = sum;
    __syncthreads();
    if (t < 64) {
        float s   = sm[t] + sm[t + 64] + sm[t + 128] + sm[t + 192];
        float avg = s * (1.f / 8192.f);
        sr[t] = -avg * __logf(fmaxf(avg, 1e-20f));
    }
    __syncthreads();
    for (int s = 32; s > 0; s >>= 1) {
        if (t < s) sr[t] += sr[t + s];
        __syncthreads();
    }
    if (t == 0) {
        g_Cp[blockIdx.x] = sr[0];
        __threadfence();
        islast = (atomicAdd(&g_cnt, 1u) == CBLK - 1) ? 1u : 0u;
    }
    __syncthreads();

    if (islast && t < 32) {
        volatile float* cp = g_Cp;
        volatile float* ap = g_Ap;
        float cb = 0.f;
#pragma unroll
        for (int i = 0; i < CBLK / 32; i++) cb += cp[t + 32 * i];
        float cm = 0.f, en = 0.f;
#pragma unroll
        for (int i = 0; i < K1B / 32; i++) {        // 256 K1 blocks
            cm += ap[2 * (t + 32 * i)];
            en += ap[2 * (t + 32 * i) + 1];
        }
#pragma unroll
        for (int o = 16; o > 0; o >>= 1) {
            cb += __shfl_down_sync(0xffffffffu, cb, o);
            cm += __shfl_down_sync(0xffffffffu, cm, o);
            en += __shfl_down_sync(0xffffffffu, en, o);
        }
        if (t == 0) {
            float ps_mean     = en / 8192.f;
            float commit_mean = cm / (8192.f * 14.f);
            dout[OUT_LOSS] = 0.1f * (ps_mean - cb) + commit_mean;
        }
    }
}

// ---------------------------------------------------------------------------
extern "C" void kernel_launch(void* const* d_in, const int* in_sizes, int n_in,
                              void* d_out, int out_size) {
    const float* x    = (const float*)d_in[0];
    const float* Win  = (const float*)d_in[1];
    const float* bin  = (const float*)d_in[2];
    const float* Wout = (const float*)d_in[3];
    const float* bout = (const float*)d_in[4];
    float* out = (float*)d_out;

    k_in_mid<<<K1B, 256>>>(x, Win, bin, out);
    k_out_avg<<<ABLK + OBLK, 512>>>(Wout, bout, out);
    k_cred_final<<<CBLK, 256>>>(out);
}

// round 17
// speedup vs baseline: 1.6178x; 1.6178x over previous
#include <cuda_runtime.h>
#include <math.h>
#include <stdint.h>

// ---------------------------------------------------------------------------
// LFQ forward, B=4, DIM=512, T=2048, codebook_dim=14, NB_CODE=16384
// d_out layout (float32): out[4*512*2048] | indices[4*2048] | aux_loss[1]
// K1: in-proj (R12 reg-batched, measured 14.4us) + mid + half-products
// K2: avg-GEMM (148 blocks, f32x2, 2-sample MLP batch) || outproj (128 blocks)
// K3: cred (split-reduction, 128 blocks) + final
// ---------------------------------------------------------------------------

#define DIM_ 512
#define T_   2048
#define N_   8192
#define C_   14
#define J_   16384
#define OUT_IDX  4194304
#define OUT_LOSS 4202496
#define ABLK 148           // avg-GEMM blocks
#define OBLK 128           // outproj blocks
#define K1B  256           // K1 blocks
#define SPB  32            // samples per K1 block
#define CBLK 128           // K3 blocks

// Static scratch (no allocations allowed)
__device__ int      g_idx[N_];
__device__ float    g_Lo[N_ * 128];        // low  7-bit half products (jl, c=13..7)
__device__ float    g_Hi[N_ * 128];        // high 7-bit half products (jh, c=6..0)
__device__ float    g_Ap[2 * K1B];         // K1 blocks x {commit, entropy}
__device__ float    g_Bp[ABLK * J_];       // partial avg_prob sums
__device__ float    g_Cp[CBLK];            // codebook-entropy partials
__device__ unsigned g_cnt;                 // K3 last-block counter (reset by K1)

__device__ __forceinline__ unsigned long long fma_f32x2(unsigned long long a,
                                                        unsigned long long b,
                                                        unsigned long long c) {
    unsigned long long d;
    asm("fma.rn.f32x2 %0, %1, %2, %3;" : "=l"(d) : "l"(a), "l"(b), "l"(c));
    return d;
}

// ---------------------------------------------------------------------------
// K1: grid = 256 blocks x 256 threads, 32 samples/block.  (R12 measured-best)
// Thread (chunk = t>>3 in [0,32), grp = t&7) accumulates 4 samples x 14 c
// over 16 d.  Loads batched 8-deep for MLP (explicit xv[8] buffer).
// ---------------------------------------------------------------------------
__global__ void __launch_bounds__(256, 2) k_in_mid(const float* __restrict__ x,
                                                   const float* __restrict__ Win,
                                                   const float* __restrict__ bin,
                                                   float* __restrict__ dout) {
    __shared__ __align__(16) float sbuf[8192];   // phase A: ws[512][16]; B: P[16][14][32]
    __shared__ float pbuf[SPB][16];
    __shared__ float cbuf[SPB][14];
    __shared__ float ebuf[SPB][14];
    __shared__ int   ibuf[SPB][14];

    int t = threadIdx.x;
    if (blockIdx.x == 0 && t == 0) g_cnt = 0;   // reset K3's counter each call

    // ws[d][c] = Win[c][d]  (transpose; reads coalesced over d)
    float (*ws)[16] = (float(*)[16])sbuf;
    for (int i = t; i < C_ * DIM_; i += 256) {
        int c = i >> 9, d = i & 511;
        ws[d][c] = Win[i];
    }
    __syncthreads();

    int chunk = t >> 3;                 // 32 chunks x 16 d
    int grp   = t & 7;                  // 8 groups x 4 samples
    int n0    = blockIdx.x * SPB;
    int nb    = n0 + grp * 4;           // first of this thread's 4 samples
    int b     = nb >> 11, tt = nb & 2047;
    const float* xp = x + ((size_t)(b * DIM_ + chunk * 16)) * T_ + tt;

    float4 acc[C_];
#pragma unroll
    for (int c = 0; c < C_; c++) acc[c] = make_float4(0.f, 0.f, 0.f, 0.f);

    float4 xv[8];
#pragma unroll
    for (int half = 0; half < 2; half++) {
        // batched loads: 8 independent LDG.128 in flight
#pragma unroll
        for (int i = 0; i < 8; i++)
            xv[i] = *reinterpret_cast<const float4*>(xp + (size_t)(half * 8 + i) * T_);
        // consume
#pragma unroll
        for (int i = 0; i < 8; i++) {
            const float4* w4 = reinterpret_cast<const float4*>(ws[chunk * 16 + half * 8 + i]);
            float4 w0 = w4[0], w1 = w4[1], w2 = w4[2], w3 = w4[3];
            float w[C_] = {w0.x, w0.y, w0.z, w0.w, w1.x, w1.y, w1.z, w1.w,
                           w2.x, w2.y, w2.z, w2.w, w3.x, w3.y};
#pragma unroll
            for (int c = 0; c < C_; c++) {
                acc[c].x += w[c] * xv[i].x;
                acc[c].y += w[c] * xv[i].y;
                acc[c].z += w[c] * xv[i].z;
                acc[c].w += w[c] * xv[i].w;
            }
        }
    }

    // ---- chunk fold 32 -> 16 in smem (reuse sbuf; all ws reads done) ----
    // P[ch][c][s] at sbuf[ch*448 + c*32 + s], ch in [0,16)
    __syncthreads();
    if (chunk >= 16) {
        float* base = sbuf + (chunk - 16) * 448 + grp * 4;
#pragma unroll
        for (int c = 0; c < C_; c++)
            *reinterpret_cast<float4*>(base + c * 32) = acc[c];
    }
    __syncthreads();
    if (chunk < 16) {
        float* base = sbuf + chunk * 448 + grp * 4;
#pragma unroll
        for (int c = 0; c < C_; c++) {
            float4 p = *reinterpret_cast<const float4*>(base + c * 32);
            acc[c].x += p.x; acc[c].y += p.y; acc[c].z += p.z; acc[c].w += p.w;
            *reinterpret_cast<float4*>(base + c * 32) = acc[c];
        }
    }
    __syncthreads();

    // ---- mid: 448 (s,c) pairs over 256 threads (2 rounds) ----
#pragma unroll
    for (int r = 0; r < 2; r++) {
        int p = t + r * 256;
        if (p < SPB * C_) {
            int c = p >> 5, s = p & 31;
            float hv = bin[c];
#pragma unroll
            for (int ch = 0; ch < 16; ch++) hv += sbuf[ch * 448 + c * 32 + s];
            bool  pos = hv > 0.f;
            float q   = pos ? 1.f : -1.f;
            float d   = hv - q;
            float z   = __expf(-400.f * fabsf(hv));   // sigmoid(400h) small-side-safe
            float pb  = 1.f / (1.f + z);
            float psm = z * pb;
            float e   = -pb * __logf(pb);
            if (psm > 0.f) e -= psm * __logf(psm);
            pbuf[s][c] = pos ? pb : psm;
            cbuf[s][c] = d * d;
            ebuf[s][c] = e;
            ibuf[s][c] = pos ? (1 << (13 - c)) : 0;
        }
    }
    __syncthreads();

    // ---- per-sample combine (warp 0) + block loss reduction ----
    if (t < SPB) {
        int idx = 0;
        float cm = 0.f, en = 0.f;
#pragma unroll
        for (int c = 0; c < C_; c++) {
            idx |= ibuf[t][c];
            cm  += cbuf[t][c];
            en  += ebuf[t][c];
        }
        g_idx[n0 + t] = idx;
        dout[OUT_IDX + n0 + t] = (float)idx;
#pragma unroll
        for (int o = 16; o > 0; o >>= 1) {
            cm += __shfl_down_sync(0xffffffffu, cm, o);
            en += __shfl_down_sync(0xffffffffu, en, o);
        }
        if (t == 0) { g_Ap[blockIdx.x * 2] = cm; g_Ap[blockIdx.x * 2 + 1] = en; }
    }

    // ---- production: warp w -> samples w*4..w*4+3 ----
    // Lo: j bit k (k<7) <-> c = 13-k.  Hi: jh bit k <-> c = 6-k.
    {
        int warp = t >> 5, lane = t & 31;
#pragma unroll
        for (int si = 0; si < 4; si++) {
            int ss = warp * 4 + si;
            float lowL = 1.f, lowH = 1.f;
#pragma unroll
            for (int k = 0; k < 5; k++) {
                float pL = pbuf[ss][13 - k];
                float pH = pbuf[ss][6 - k];
                bool bit = (lane >> k) & 1;
                lowL *= bit ? pL : (1.f - pL);
                lowH *= bit ? pH : (1.f - pH);
            }
            float p5L = pbuf[ss][8], p6L = pbuf[ss][7];
            float p5H = pbuf[ss][1], p6H = pbuf[ss][0];
            float qL[4] = { (1.f - p5L) * (1.f - p6L), p5L * (1.f - p6L),
                            (1.f - p5L) * p6L,         p5L * p6L };
            float qH[4] = { (1.f - p5H) * (1.f - p6H), p5H * (1.f - p6H),
                            (1.f - p5H) * p6H,         p5H * p6H };
            float* lp = g_Lo + (size_t)(n0 + ss) * 128 + lane;
            float* hp = g_Hi + (size_t)(n0 + ss) * 128 + lane;
#pragma unroll
            for (int q = 0; q < 4; q++) {
                lp[q * 32] = lowL * qL[q];
                hp[q * 32] = lowH * qH[q];
            }
        }
    }
}

// ---------------------------------------------------------------------------
// K2: blocks 0..147 = avg-GEMM (f32x2, 2-sample MLP batch),
//     blocks 148..275 = outproj (64 d-rows).  grid = 276 x 512, 2 blocks/SM
// ---------------------------------------------------------------------------
__global__ void __launch_bounds__(512, 2) k_out_avg(const float* __restrict__ Wout,
                                                    const float* __restrict__ bout,
                                                    float* __restrict__ out) {
    __shared__ float ws2[64][16];
    __shared__ float bo[64];
    int t = threadIdx.x;

    if (blockIdx.x < ABLK) {
        // ---- avg outer product, f32x2-packed, 2 samples per iter (MLP=6) ----
        int bb = blockIdx.x;
        int ns = (bb * N_) / ABLK;
        int ne = ((bb + 1) * N_) / ABLK;
        int cnt = ne - ns;
        int jl0 = (t & 31) * 4;
        int jh0 = (t >> 5) * 8;

        const float* lo = g_Lo + (size_t)ns * 128 + jl0;
        const float* hi = g_Hi + (size_t)ns * 128 + jh0;

        unsigned long long A[4][4];
#pragma unroll
        for (int p = 0; p < 4; p++)
#pragma unroll
            for (int j = 0; j < 4; j++) A[p][j] = 0ull;

        int k = 0;
        for (; k + 1 < cnt; k += 2, lo += 256, hi += 256) {
            // issue all 6 loads first (MLP)
            float4     la   = *reinterpret_cast<const float4*>(lo);
            ulonglong2 ha01 = *reinterpret_cast<const ulonglong2*>(hi);
            ulonglong2 ha23 = *reinterpret_cast<const ulonglong2*>(hi + 4);
            float4     lb   = *reinterpret_cast<const float4*>(lo + 128);
            ulonglong2 hb01 = *reinterpret_cast<const ulonglong2*>(hi + 128);
            ulonglong2 hb23 = *reinterpret_cast<const ulonglong2*>(hi + 132);

            unsigned long long hpa[4] = {ha01.x, ha01.y, ha23.x, ha23.y};
            unsigned long long lda[4];
            asm("mov.b64 %0, {%1, %1};" : "=l"(lda[0]) : "f"(la.x));
            asm("mov.b64 %0, {%1, %1};" : "=l"(lda[1]) : "f"(la.y));
            asm("mov.b64 %0, {%1, %1};" : "=l"(lda[2]) : "f"(la.z));
            asm("mov.b64 %0, {%1, %1};" : "=l"(lda[3]) : "f"(la.w));
#pragma unroll
            for (int p = 0; p < 4; p++)
#pragma unroll
                for (int j = 0; j < 4; j++)
                    A[p][j] = fma_f32x2(hpa[p], lda[j], A[p][j]);

            unsigned long long hpb[4] = {hb01.x, hb01.y, hb23.x, hb23.y};
            unsigned long long ldb[4];
            asm("mov.b64 %0, {%1, %1};" : "=l"(ldb[0]) : "f"(lb.x));
            asm("mov.b64 %0, {%1, %1};" : "=l"(ldb[1]) : "f"(lb.y));
            asm("mov.b64 %0, {%1, %1};" : "=l"(ldb[2]) : "f"(lb.z));
            asm("mov.b64 %0, {%1, %1};" : "=l"(ldb[3]) : "f"(lb.w));
#pragma unroll
            for (int p = 0; p < 4; p++)
#pragma unroll
                for (int j = 0; j < 4; j++)
                    A[p][j] = fma_f32x2(hpb[p], ldb[j], A[p][j]);
        }
        if (k < cnt) {   // odd tail
            float4     la   = *reinterpret_cast<const float4*>(lo);
            ulonglong2 ha01 = *reinterpret_cast<const ulonglong2*>(hi);
            ulonglong2 ha23 = *reinterpret_cast<const ulonglong2*>(hi + 4);
            unsigned long long hpa[4] = {ha01.x, ha01.y, ha23.x, ha23.y};
            unsigned long long lda[4];
            asm("mov.b64 %0, {%1, %1};" : "=l"(lda[0]) : "f"(la.x));
            asm("mov.b64 %0, {%1, %1};" : "=l"(lda[1]) : "f"(la.y));
            asm("mov.b64 %0, {%1, %1};" : "=l"(lda[2]) : "f"(la.z));
            asm("mov.b64 %0, {%1, %1};" : "=l"(lda[3]) : "f"(la.w));
#pragma unroll
            for (int p = 0; p < 4; p++)
#pragma unroll
                for (int j = 0; j < 4; j++)
                    A[p][j] = fma_f32x2(hpa[p], lda[j], A[p][j]);
        }

        float* bp = g_Bp + (size_t)bb * J_;
#pragma unroll
        for (int p = 0; p < 4; p++) {
            float r0[4], r1[4];
#pragma unroll
            for (int j = 0; j < 4; j++)
                asm("mov.b64 {%0, %1}, %2;" : "=f"(r0[j]), "=f"(r1[j]) : "l"(A[p][j]));
            *reinterpret_cast<float4*>(&bp[(jh0 + 2 * p) * 128 + jl0]) =
                make_float4(r0[0], r0[1], r0[2], r0[3]);
            *reinterpret_cast<float4*>(&bp[(jh0 + 2 * p + 1) * 128 + jl0]) =
                make_float4(r1[0], r1[1], r1[2], r1[3]);
        }
    } else {
        // ---- out-projection: 128 blocks, thread = sample, 64 d-rows ----
        int ob    = blockIdx.x - ABLK;
        int hch   = ob & 7;
        int tile  = ob >> 3;
        int d0    = hch * 64;
        for (int i = t; i < 64 * 16; i += 512) {
            int dd = i >> 4, c = i & 15;
            ws2[dd][c] = (c < C_) ? Wout[(d0 + dd) * C_ + c] : 0.f;
        }
        if (t < 64) bo[t] = bout[d0 + t];
        __syncthreads();

        int n = tile * 512 + t;
        int b = n >> 11, tt = n & 2047;
        int idx = g_idx[n];
        float sv[C_];
#pragma unroll
        for (int c = 0; c < C_; c++) sv[c] = ((idx >> (13 - c)) & 1) ? 1.f : -1.f;

        float* op = out + ((size_t)(b * DIM_ + d0)) * T_ + tt;
#pragma unroll 2
        for (int dd = 0; dd < 64; dd++) {
            const float4* w4 = reinterpret_cast<const float4*>(ws2[dd]);
            float4 w0 = w4[0], w1 = w4[1], w2 = w4[2], w3 = w4[3];
            float r = bo[dd];
            r += w0.x * sv[0]  + w0.y * sv[1]  + w0.z * sv[2]  + w0.w * sv[3];
            r += w1.x * sv[4]  + w1.y * sv[5]  + w1.z * sv[6]  + w1.w * sv[7];
            r += w2.x * sv[8]  + w2.y * sv[9]  + w2.z * sv[10] + w2.w * sv[11];
            r += w3.x * sv[12] + w3.y * sv[13];
            op[(size_t)dd * T_] = r;
        }
    }
}

// ---------------------------------------------------------------------------
// K3: reduce g_Bp -> avg_prob -> codebook-entropy partials; last block combines
// grid = 128 blocks x 256 threads; two thread-halves split the 148-partial sum
// ---------------------------------------------------------------------------
__global__ void __launch_bounds__(256) k_cred_final(float* __restrict__ dout) {
    int t = threadIdx.x;
    int e = blockIdx.x * 128 + (t & 127);
    int half = t >> 7;                       // 0: p in [0,74), 1: p in [74,148)
    float sum = 0.f;
#pragma unroll 4
    for (int p = half * 74; p < half * 74 + 74; p++)
        sum += g_Bp[(size_t)p * J_ + e];

    __shared__ float sr2[256];
    __shared__ float sr[128];
    __shared__ unsigned islast;
    sr2[t] = sum;
    __syncthreads();
    if (t < 128) {
        float s    = sr2[t] + sr2[t + 128];
        float avg  = s * (1.f / 8192.f);
        sr[t] = -avg * __logf(fmaxf(avg, 1e-20f));
    }
    __syncthreads();
    for (int s = 64; s > 0; s >>= 1) {
        if (t < s) sr[t] += sr[t + s];
        __syncthreads();
    }
    if (t == 0) {
        g_Cp[blockIdx.x] = sr[0];
        __threadfence();
        islast = (atomicAdd(&g_cnt, 1u) == CBLK - 1) ? 1u : 0u;
    }
    __syncthreads();

    if (islast && t < 32) {
        volatile float* cp = g_Cp;
        volatile float* ap = g_Ap;
        float cb = cp[t] + cp[t + 32] + cp[t + 64] + cp[t + 96];
        float cm = 0.f, en = 0.f;
#pragma unroll
        for (int i = 0; i < K1B / 32; i++) {        // 256 K1 blocks
            cm += ap[2 * (t + 32 * i)];
            en += ap[2 * (t + 32 * i) + 1];
        }
#pragma unroll
        for (int o = 16; o > 0; o >>= 1) {
            cb += __shfl_down_sync(0xffffffffu, cb, o);
            cm += __shfl_down_sync(0xffffffffu, cm, o);
            en += __shfl_down_sync(0xffffffffu, en, o);
        }
        if (t == 0) {
            float ps_mean     = en / 8192.f;
            float commit_mean = cm / (8192.f * 14.f);
            dout[OUT_LOSS] = 0.1f * (ps_mean - cb) + commit_mean;
        }
    }
}

// ---------------------------------------------------------------------------
extern "C" void kernel_launch(void* const* d_in, const int* in_sizes, int n_in,
                              void* d_out, int out_size) {
    const float* x    = (const float*)d_in[0];
    const float* Win  = (const float*)d_in[1];
    const float* bin  = (const float*)d_in[2];
    const float* Wout = (const float*)d_in[3];
    const float* bout = (const float*)d_in[4];
    float* out = (float*)d_out;

    k_in_mid<<<K1B, 256>>>(x, Win, bin, out);
    k_out_avg<<<ABLK + OBLK, 512>>>(Wout, bout, out);
    k_cred_final<<<CBLK, 256>>>(out);
}